// round 1
// baseline (speedup 1.0000x reference)
#include <cuda_runtime.h>

// Problem constants (fixed by the dataset)
#define Nn 8
#define Kk 16
#define Hh 256
#define Ww 256
#define Cc 4
#define Pp 100000
#define HW (Hh * Ww)          // 65536
#define NPIX (Nn * HW)        // 524288

// Scratch: ptclds transposed to AoS (P x float4), lives in device global memory
// (no allocation — rules-compliant __device__ array).
__device__ float4 g_ptcld_aos[Pp];

// Kernel 1: transpose (C,P) -> AoS float4[P]
__global__ void transpose_ptcld_kernel(const float* __restrict__ ptclds) {
    int i = blockIdx.x * blockDim.x + threadIdx.x;
    if (i < Pp) {
        float4 v;
        v.x = ptclds[0 * Pp + i];
        v.y = ptclds[1 * Pp + i];
        v.z = ptclds[2 * Pp + i];
        v.w = ptclds[3 * Pp + i];
        g_ptcld_aos[i] = v;
    }
}

// Kernel 2: one thread per pixel, front-to-back alpha composite with
// early break on the z-sorted -1 sentinel.
__global__ __launch_bounds__(256) void composite_kernel(
    const int*   __restrict__ fragments,   // (N,K,H,W)
    const float* __restrict__ alphas,      // (N,K,H,W)
    const float* __restrict__ background,  // (3,)
    float*       __restrict__ out)         // (N,C,H,W)
{
    int pix = blockIdx.x * blockDim.x + threadIdx.x;
    if (pix >= NPIX) return;

    int n  = pix >> 16;          // pix / HW
    int hw = pix & (HW - 1);     // pix % HW

    const int base = n * (Kk * HW) + hw;
    float* outp = out + n * (Cc * HW) + hw;

    int f0 = fragments[base];
    if (f0 < 0) {
        // background fill (rgb from background_color, alpha = 1)
        outp[0 * HW] = background[0];
        outp[1 * HW] = background[1];
        outp[2 * HW] = background[2];
        outp[3 * HW] = 1.0f;
        return;
    }

    float T = 1.0f;
    float r = 0.f, g = 0.f, b = 0.f, aa = 0.f;

    int f = f0;
    #pragma unroll 1
    for (int k = 0; k < Kk; ++k) {
        float a = alphas[base + k * HW];
        float w = a * T;
        T *= (1.0f - a);
        float4 p = g_ptcld_aos[f];
        r  = fmaf(w, p.x, r);
        g  = fmaf(w, p.y, g);
        b  = fmaf(w, p.z, b);
        aa = fmaf(w, p.w, aa);
        if (k + 1 < Kk) {
            f = fragments[base + (k + 1) * HW];
            if (f < 0) break;   // z-sorted: trailing slots are all -1
        }
    }

    outp[0 * HW] = r;
    outp[1 * HW] = g;
    outp[2 * HW] = b;
    outp[3 * HW] = aa;
}

extern "C" void kernel_launch(void* const* d_in, const int* in_sizes, int n_in,
                              void* d_out, int out_size) {
    const int*   fragments  = (const int*)  d_in[0];  // (N,K,H,W) int32
    const float* alphas     = (const float*)d_in[1];  // (N,K,H,W) f32
    const float* ptclds     = (const float*)d_in[2];  // (C,P) f32
    const float* background = (const float*)d_in[3];  // (3,) f32
    float* out = (float*)d_out;                       // (N,C,H,W) f32

    transpose_ptcld_kernel<<<(Pp + 255) / 256, 256>>>(ptclds);
    composite_kernel<<<NPIX / 256, 256>>>(fragments, alphas, background, out);
}

// round 2
// speedup vs baseline: 1.0779x; 1.0779x over previous
#include <cuda_runtime.h>

// Problem constants (fixed by the dataset)
#define Nn 8
#define Kk 16
#define Hh 256
#define Ww 256
#define Cc 4
#define Pp 100000
#define HW (Hh * Ww)          // 65536
#define NPIX (Nn * HW)        // 524288
#define CHUNK 4

// Scratch: ptclds transposed to AoS (P x float4) — __device__ global, no alloc.
__device__ float4 g_ptcld_aos[Pp];

// Kernel 1: transpose (C,P) -> AoS float4[P]
__global__ void transpose_ptcld_kernel(const float* __restrict__ ptclds) {
    int i = blockIdx.x * blockDim.x + threadIdx.x;
    if (i < Pp) {
        float4 v;
        v.x = ptclds[0 * Pp + i];
        v.y = ptclds[1 * Pp + i];
        v.z = ptclds[2 * Pp + i];
        v.w = ptclds[3 * Pp + i];
        g_ptcld_aos[i] = v;
    }
}

// Kernel 2: 2 pixels per thread, K chunked by 4 for memory-level parallelism.
__global__ __launch_bounds__(256) void composite_kernel(
    const int*   __restrict__ fragments,   // (N,K,H,W)
    const float* __restrict__ alphas,      // (N,K,H,W)
    const float* __restrict__ background,  // (3,)
    float*       __restrict__ out)         // (N,C,H,W)
{
    int t = blockIdx.x * blockDim.x + threadIdx.x;   // 0 .. NPIX/2-1
    int pix0 = t << 1;                               // even pixel index
    int n  = pix0 >> 16;                             // pix0 / HW
    int hw = pix0 & (HW - 1);                        // pix0 % HW

    const int base = n * (Kk * HW) + hw;
    float* outp = out + n * (Cc * HW) + hw;

    float bgr = background[0], bgg = background[1], bgb = background[2];

    // Accumulators for the two pixels
    float T0 = 1.f, r0 = 0.f, g0 = 0.f, b0 = 0.f, a0 = 0.f;
    float T1 = 1.f, r1 = 0.f, g1 = 0.f, b1 = 0.f, a1 = 0.f;
    int bg0 = 0, bg1 = 0;   // set from k=0 fragment

    #pragma unroll 1
    for (int k0 = 0; k0 < Kk; k0 += CHUNK) {
        // Batch-issue independent loads: 4 frag pairs + 4 alpha pairs in flight
        int2   f[CHUNK];
        float2 a[CHUNK];
        #pragma unroll
        for (int j = 0; j < CHUNK; ++j) {
            f[j] = *(const int2*)  (fragments + base + (k0 + j) * HW);
            a[j] = *(const float2*)(alphas    + base + (k0 + j) * HW);
        }

        // Issue all gathers before consuming (up to 8 independent L2 gathers)
        float4 p0[CHUNK], p1[CHUNK];
        #pragma unroll
        for (int j = 0; j < CHUNK; ++j) {
            if (f[j].x >= 0) p0[j] = __ldg(&g_ptcld_aos[f[j].x]);
            if (f[j].y >= 0) p1[j] = __ldg(&g_ptcld_aos[f[j].y]);
        }

        if (k0 == 0) { bg0 = (f[0].x < 0); bg1 = (f[0].y < 0); }

        // Serial compositing math (cheap FMAs)
        #pragma unroll
        for (int j = 0; j < CHUNK; ++j) {
            if (f[j].x >= 0) {
                float w = a[j].x * T0;  T0 *= (1.0f - a[j].x);
                r0 = fmaf(w, p0[j].x, r0);  g0 = fmaf(w, p0[j].y, g0);
                b0 = fmaf(w, p0[j].z, b0);  a0 = fmaf(w, p0[j].w, a0);
            }
            if (f[j].y >= 0) {
                float w = a[j].y * T1;  T1 *= (1.0f - a[j].y);
                r1 = fmaf(w, p1[j].x, r1);  g1 = fmaf(w, p1[j].y, g1);
                b1 = fmaf(w, p1[j].z, b1);  a1 = fmaf(w, p1[j].w, a1);
            }
        }

        // z-sorted: if the last slot of the chunk is invalid for both pixels,
        // all later slots are invalid too.
        if ((f[CHUNK-1].x | f[CHUNK-1].y) < 0 && f[CHUNK-1].x < 0 && f[CHUNK-1].y < 0)
            break;
    }

    // Background fill where no nearest point exists
    if (bg0) { r0 = bgr; g0 = bgg; b0 = bgb; a0 = 1.0f; }
    if (bg1) { r1 = bgr; g1 = bgg; b1 = bgb; a1 = 1.0f; }

    // Vectorized stores: two adjacent pixels per channel
    *(float2*)(outp + 0 * HW) = make_float2(r0, r1);
    *(float2*)(outp + 1 * HW) = make_float2(g0, g1);
    *(float2*)(outp + 2 * HW) = make_float2(b0, b1);
    *(float2*)(outp + 3 * HW) = make_float2(a0, a1);
}

extern "C" void kernel_launch(void* const* d_in, const int* in_sizes, int n_in,
                              void* d_out, int out_size) {
    const int*   fragments  = (const int*)  d_in[0];  // (N,K,H,W) int32
    const float* alphas     = (const float*)d_in[1];  // (N,K,H,W) f32
    const float* ptclds     = (const float*)d_in[2];  // (C,P) f32
    const float* background = (const float*)d_in[3];  // (3,) f32
    float* out = (float*)d_out;                       // (N,C,H,W) f32

    transpose_ptcld_kernel<<<(Pp + 255) / 256, 256>>>(ptclds);
    composite_kernel<<<(NPIX / 2) / 256, 256>>>(fragments, alphas, background, out);
}